// round 1
// baseline (speedup 1.0000x reference)
#include <cuda_runtime.h>
#include <cstdint>

// Problem constants
#define NB   32      // batch
#define CI   256     // in channels
#define CO   256     // out channels
#define HH   56
#define WW   56
#define HWSZ (HH*WW)       // 3136
#define CW   8             // 256 ch / 32 bits
#define NTAP 9

// Scratch (device globals; no allocation allowed)
__device__ unsigned g_Apk[NB * CW * HWSZ];      // packed activations [n][cw][h][w]
__device__ unsigned g_Wpk[CO * NTAP * CW];      // packed weights    [o][tap][cw]
__device__ int      g_PW [CO * NTAP];           // per (o,tap) popcount of weight bits

// ---------------------------------------------------------------------------
// Pack activations: bit c set iff x[n][cw*32+c][h][w] >= 0
// word layout [n][cw][hw]; consecutive threads = consecutive hw -> coalesced.
__global__ void pack_x_kernel(const float* __restrict__ x) {
    int idx = blockIdx.x * blockDim.x + threadIdx.x;
    if (idx >= NB * CW * HWSZ) return;
    int hw = idx % HWSZ;
    int t  = idx / HWSZ;
    int cw = t % CW;
    int n  = t / CW;
    const float* xp = x + ((size_t)(n * CI + cw * 32)) * HWSZ + hw;
    unsigned bits = 0;
#pragma unroll
    for (int c = 0; c < 32; c++) {
        bits |= (xp[(size_t)c * HWSZ] >= 0.0f ? 1u : 0u) << c;
    }
    g_Apk[idx] = bits;
}

// ---------------------------------------------------------------------------
// Pack weights: word (o,tap,cw); bit c set iff M[o][cw*32+c][tap] >= 0
__global__ void pack_w_kernel(const float* __restrict__ M) {
    int idx = blockIdx.x * blockDim.x + threadIdx.x;
    if (idx >= CO * NTAP * CW) return;
    int cw  = idx % CW;
    int t   = idx / CW;
    int tap = t % NTAP;
    int o   = t / NTAP;
    unsigned bits = 0;
#pragma unroll
    for (int c = 0; c < 32; c++) {
        float v = M[((size_t)(o * CI + cw * 32 + c)) * NTAP + tap];
        bits |= (v >= 0.0f ? 1u : 0u) << c;
    }
    g_Wpk[idx] = bits;
}

// Per (o,tap) total weight popcount (for border correction)
__global__ void pw_kernel() {
    int idx = blockIdx.x * blockDim.x + threadIdx.x;
    if (idx >= CO * NTAP) return;
    int s = 0;
#pragma unroll
    for (int cw = 0; cw < CW; cw++) s += __popc(g_Wpk[idx * CW + cw]);
    g_PW[idx] = s;
}

// ---------------------------------------------------------------------------
// Main conv: block = (h-tile of 4 rows, n). 224 threads, 1 pixel each.
// Loops all 256 output channels in groups of OG=16.
#define TH 4
#define OG 16
#define NTHREADS (WW * TH)   // 224

__global__ __launch_bounds__(NTHREADS)
void bconv_kernel(const float* __restrict__ alpha, float* __restrict__ out) {
    __shared__ __align__(16) unsigned Asm[TH + 2][WW + 2][CW];  // zero-padded tile
    __shared__ __align__(16) unsigned Wsm[OG][NTAP][CW];
    __shared__ int   PWsm[OG][NTAP];
    __shared__ float Alp[OG];

    const int tid = threadIdx.x;
    const int h0  = blockIdx.x * TH;
    const int n   = blockIdx.y;

    // --- stage activation tile (zero-padded) ---
    // iterate [cw][row][col] so global reads are coalesced along col
    const int SITES = (TH + 2) * (WW + 2);          // 348
    for (int i = tid; i < CW * SITES; i += NTHREADS) {
        int cw  = i / SITES;
        int s   = i % SITES;
        int row = s / (WW + 2);
        int col = s % (WW + 2);
        int gh  = h0 - 1 + row;
        int gw  = col - 1;
        unsigned v = 0;
        if (gh >= 0 && gh < HH && gw >= 0 && gw < WW)
            v = g_Apk[(n * CW + cw) * HWSZ + gh * WW + gw];
        Asm[row][col][cw] = v;
    }

    const int tx = tid % WW;        // w
    const int ty = tid / WW;        // 0..3
    const int h  = h0 + ty;
    const int w  = tx;

    const int nrows = 1 + (h > 0) + (h < HH - 1);
    const int ncols = 1 + (w > 0) + (w < WW - 1);
    const int nv    = nrows * ncols;
    const int hw    = h * WW + w;

    for (int og = 0; og < CO / OG; og++) {
        __syncthreads();   // A-tile ready (first iter) / prev group reads done
        // stage weights for this o-group
        const int obase = og * OG;
        for (int i = tid; i < OG * NTAP * CW; i += NTHREADS)
            ((unsigned*)Wsm)[i] = g_Wpk[obase * NTAP * CW + i];
        for (int i = tid; i < OG * NTAP; i += NTHREADS)
            ((int*)PWsm)[i] = g_PW[obase * NTAP + i];
        if (tid < OG) Alp[tid] = alpha[obase + tid];
        __syncthreads();

        int acc[OG];
#pragma unroll
        for (int o = 0; o < OG; o++) acc[o] = 0;

#pragma unroll 1
        for (int tap = 0; tap < NTAP; tap++) {
            const int dy = tap / 3;
            const int dx = tap - dy * 3;
            const uint4* ap = (const uint4*)&Asm[ty + dy][tx + dx][0];
            const uint4 a0 = ap[0];
            const uint4 a1 = ap[1];
#pragma unroll
            for (int o = 0; o < OG; o++) {
                const uint4* wp = (const uint4*)&Wsm[o][tap][0];
                const uint4 w0 = wp[0];
                const uint4 w1 = wp[1];
                int s = __popc(a0.x ^ w0.x);
                s += __popc(a0.y ^ w0.y);
                s += __popc(a0.z ^ w0.z);
                s += __popc(a0.w ^ w0.w);
                s += __popc(a1.x ^ w1.x);
                s += __popc(a1.y ^ w1.y);
                s += __popc(a1.z ^ w1.z);
                s += __popc(a1.w ^ w1.w);
                acc[o] += s;
            }
        }

        // write outputs (border correction only when needed)
#pragma unroll
        for (int o = 0; o < OG; o++) {
            int corr = 0;
            if (nv != 9) {
#pragma unroll
                for (int tap = 0; tap < NTAP; tap++) {
                    int dy = tap / 3 - 1;
                    int dx = tap % 3 - 1;
                    int gh = h + dy, gw = w + dx;
                    bool valid = (gh >= 0) && (gh < HH) && (gw >= 0) && (gw < WW);
                    if (!valid) corr += PWsm[o][tap];
                }
            }
            float val = Alp[o] * (float)(nv * 256 - 2 * acc[o] + 2 * corr);
            out[((size_t)(n * CO + obase + o)) * HWSZ + hw] = val;
        }
    }
}

// ---------------------------------------------------------------------------
extern "C" void kernel_launch(void* const* d_in, const int* in_sizes, int n_in,
                              void* d_out, int out_size) {
    const float* x     = (const float*)d_in[0];   // (32,256,56,56)
    const float* M     = (const float*)d_in[1];   // (256,256,3,3)
    const float* alpha = (const float*)d_in[2];   // (256,1,1)
    float* out         = (float*)d_out;           // (32,256,56,56)

    {
        int total = NB * CW * HWSZ;               // 802816
        pack_x_kernel<<<(total + 255) / 256, 256>>>(x);
    }
    {
        int total = CO * NTAP * CW;               // 18432
        pack_w_kernel<<<(total + 127) / 128, 128>>>(M);
    }
    {
        int total = CO * NTAP;                    // 2304
        pw_kernel<<<(total + 127) / 128, 128>>>();
    }
    {
        dim3 grid(HH / TH, NB);                   // (14, 32)
        bconv_kernel<<<grid, NTHREADS>>>(alpha, out);
    }
}

// round 2
// speedup vs baseline: 1.1834x; 1.1834x over previous
#include <cuda_runtime.h>
#include <cstdint>

// Problem constants
#define NB   32      // batch
#define CI   256     // in channels
#define CO   256     // out channels
#define HH   56
#define WW   56
#define HWSZ (HH*WW)       // 3136
#define CW   8             // 256 ch / 32 bits
#define NTAP 9

// Scratch (device globals; no allocation allowed)
__device__ unsigned g_Apk[NB * CW * HWSZ];      // packed activations [n][cw][h][w]
__device__ unsigned g_Wpk[CO * NTAP * CW];      // packed weights    [o][tap][cw]
__device__ int      g_PW [CO * NTAP];           // per (o,tap) popcount of weight bits

// ---------------------------------------------------------------------------
// Pack activations: bit c set iff x[n][cw*32+c][h][w] >= 0
__global__ void pack_x_kernel(const float* __restrict__ x) {
    int idx = blockIdx.x * blockDim.x + threadIdx.x;
    if (idx >= NB * CW * HWSZ) return;
    int hw = idx % HWSZ;
    int t  = idx / HWSZ;
    int cw = t % CW;
    int n  = t / CW;
    const float* xp = x + ((size_t)(n * CI + cw * 32)) * HWSZ + hw;
    unsigned bits = 0;
#pragma unroll
    for (int c = 0; c < 32; c++) {
        bits |= (xp[(size_t)c * HWSZ] >= 0.0f ? 1u : 0u) << c;
    }
    g_Apk[idx] = bits;
}

// ---------------------------------------------------------------------------
// Pack weights: word (o,tap,cw); bit c set iff M[o][cw*32+c][tap] >= 0
__global__ void pack_w_kernel(const float* __restrict__ M) {
    int idx = blockIdx.x * blockDim.x + threadIdx.x;
    if (idx >= CO * NTAP * CW) return;
    int cw  = idx % CW;
    int t   = idx / CW;
    int tap = t % NTAP;
    int o   = t / NTAP;
    unsigned bits = 0;
#pragma unroll
    for (int c = 0; c < 32; c++) {
        float v = M[((size_t)(o * CI + cw * 32 + c)) * NTAP + tap];
        bits |= (v >= 0.0f ? 1u : 0u) << c;
    }
    g_Wpk[idx] = bits;
}

// Per (o,tap) total weight popcount (for border correction)
__global__ void pw_kernel() {
    int idx = blockIdx.x * blockDim.x + threadIdx.x;
    if (idx >= CO * NTAP) return;
    int s = 0;
#pragma unroll
    for (int cw = 0; cw < CW; cw++) s += __popc(g_Wpk[idx * CW + cw]);
    g_PW[idx] = s;
}

// ---------------------------------------------------------------------------
// Main conv.
//  grid = (HH/TH, NB, NZ); each block: 4-row tile of one image, 64 o-channels.
//  All weights for the block's 64 o-channels staged ONCE -> single barrier.
#define TH  4
#define OG  16                 // o-channels per accumulator group
#define NZ  4                  // grid.z split of output channels
#define OPB (CO / NZ)          // 64 o-channels per block
#define NTHREADS (WW * TH)     // 224

__global__ __launch_bounds__(NTHREADS, 5)
void bconv_kernel(const float* __restrict__ alpha, float* __restrict__ out) {
    __shared__ __align__(16) unsigned Asm[TH + 2][WW + 2][CW];   // 11,136 B
    __shared__ __align__(16) unsigned Wsm[OPB][NTAP][CW];        // 18,432 B
    __shared__ int   PWsm[OPB][NTAP];                            //  2,304 B
    __shared__ float Alp[OPB];                                   //    256 B

    const int tid   = threadIdx.x;
    const int h0    = blockIdx.x * TH;
    const int n     = blockIdx.y;
    const int obase0 = blockIdx.z * OPB;

    // --- stage activation tile (zero-padded) ---
    const int SITES = (TH + 2) * (WW + 2);          // 348
    for (int i = tid; i < CW * SITES; i += NTHREADS) {
        int cw  = i / SITES;
        int s   = i % SITES;
        int row = s / (WW + 2);
        int col = s % (WW + 2);
        int gh  = h0 - 1 + row;
        int gw  = col - 1;
        unsigned v = 0;
        if (gh >= 0 && gh < HH && gw >= 0 && gw < WW)
            v = g_Apk[(n * CW + cw) * HWSZ + gh * WW + gw];
        Asm[row][col][cw] = v;
    }
    // --- stage ALL weights for this block's 64 o-channels ---
    for (int i = tid; i < OPB * NTAP * CW; i += NTHREADS)
        ((unsigned*)Wsm)[i] = g_Wpk[obase0 * NTAP * CW + i];
    for (int i = tid; i < OPB * NTAP; i += NTHREADS)
        ((int*)PWsm)[i] = g_PW[obase0 * NTAP + i];
    for (int i = tid; i < OPB; i += NTHREADS)
        Alp[i] = alpha[obase0 + i];

    __syncthreads();   // the ONLY barrier in this kernel

    const int tx = tid % WW;        // w
    const int ty = tid / WW;        // 0..3
    const int h  = h0 + ty;
    const int w  = tx;

    const int nrows = 1 + (h > 0) + (h < HH - 1);
    const int ncols = 1 + (w > 0) + (w < WW - 1);
    const int nv    = nrows * ncols;
    const int hw    = h * WW + w;
    const bool border = (nv != 9);

#pragma unroll 1
    for (int og = 0; og < OPB / OG; og++) {
        const int olocal = og * OG;

        int acc[OG];
#pragma unroll
        for (int o = 0; o < OG; o++) acc[o] = 0;

#pragma unroll 1
        for (int tap = 0; tap < NTAP; tap++) {
            const int dy = tap / 3;
            const int dx = tap - dy * 3;
            const uint4* ap = (const uint4*)&Asm[ty + dy][tx + dx][0];
            const uint4 a0 = ap[0];
            const uint4 a1 = ap[1];
#pragma unroll
            for (int o = 0; o < OG; o++) {
                const uint4* wp = (const uint4*)&Wsm[olocal + o][tap][0];
                const uint4 w0 = wp[0];
                const uint4 w1 = wp[1];
                int s0 = __popc(a0.x ^ w0.x) + __popc(a0.y ^ w0.y);
                int s1 = __popc(a0.z ^ w0.z) + __popc(a0.w ^ w0.w);
                int s2 = __popc(a1.x ^ w1.x) + __popc(a1.y ^ w1.y);
                int s3 = __popc(a1.z ^ w1.z) + __popc(a1.w ^ w1.w);
                acc[o] += (s0 + s1) + (s2 + s3);
            }
        }

        // write outputs (border correction only when needed)
#pragma unroll
        for (int o = 0; o < OG; o++) {
            int corr = 0;
            if (border) {
#pragma unroll
                for (int tap = 0; tap < NTAP; tap++) {
                    int dy = tap / 3 - 1;
                    int dx = tap % 3 - 1;
                    int gh = h + dy, gw = w + dx;
                    bool valid = (gh >= 0) && (gh < HH) && (gw >= 0) && (gw < WW);
                    if (!valid) corr += PWsm[olocal + o][tap];
                }
            }
            float val = Alp[olocal + o] * (float)(nv * 256 - 2 * acc[o] + 2 * corr);
            out[((size_t)(n * CO + obase0 + olocal + o)) * HWSZ + hw] = val;
        }
    }
}

// ---------------------------------------------------------------------------
extern "C" void kernel_launch(void* const* d_in, const int* in_sizes, int n_in,
                              void* d_out, int out_size) {
    const float* x     = (const float*)d_in[0];   // (32,256,56,56)
    const float* M     = (const float*)d_in[1];   // (256,256,3,3)
    const float* alpha = (const float*)d_in[2];   // (256,1,1)
    float* out         = (float*)d_out;           // (32,256,56,56)

    {
        int total = NB * CW * HWSZ;               // 802816
        pack_x_kernel<<<(total + 255) / 256, 256>>>(x);
    }
    {
        int total = CO * NTAP * CW;               // 18432
        pack_w_kernel<<<(total + 127) / 128, 128>>>(M);
    }
    {
        int total = CO * NTAP;                    // 2304
        pw_kernel<<<(total + 127) / 128, 128>>>();
    }
    {
        dim3 grid(HH / TH, NB, NZ);               // (14, 32, 4) = 1792 blocks
        bconv_kernel<<<grid, NTHREADS>>>(alpha, out);
    }
}

// round 3
// speedup vs baseline: 1.1857x; 1.0020x over previous
#include <cuda_runtime.h>
#include <cstdint>

// Problem constants
#define NB   32      // batch
#define CI   256     // in channels
#define CO   256     // out channels
#define HH   56
#define WW   56
#define HWSZ (HH*WW)       // 3136
#define CW   8             // 256 ch / 32 bits
#define NTAP 9

// Scratch (device globals; no allocation allowed)
__device__ unsigned g_Apk[NB * CW * HWSZ];      // packed activations [n][cw][h][w]
__device__ unsigned g_Wpk[CO * NTAP * CW];      // packed weights    [o][tap][cw]
__device__ int      g_PW [CO * NTAP];           // per (o,tap) popcount of weight bits

// ---------------------------------------------------------------------------
// Pack activations: bit c set iff x[n][cw*32+c][h][w] >= 0
__global__ void pack_x_kernel(const float* __restrict__ x) {
    int idx = blockIdx.x * blockDim.x + threadIdx.x;
    if (idx >= NB * CW * HWSZ) return;
    int hw = idx % HWSZ;
    int t  = idx / HWSZ;
    int cw = t % CW;
    int n  = t / CW;
    const float* xp = x + ((size_t)(n * CI + cw * 32)) * HWSZ + hw;
    unsigned bits = 0;
#pragma unroll
    for (int c = 0; c < 32; c++) {
        bits |= (xp[(size_t)c * HWSZ] >= 0.0f ? 1u : 0u) << c;
    }
    g_Apk[idx] = bits;
}

// ---------------------------------------------------------------------------
// Pack weights: word (o,tap,cw); bit c set iff M[o][cw*32+c][tap] >= 0
__global__ void pack_w_kernel(const float* __restrict__ M) {
    int idx = blockIdx.x * blockDim.x + threadIdx.x;
    if (idx >= CO * NTAP * CW) return;
    int cw  = idx % CW;
    int t   = idx / CW;
    int tap = t % NTAP;
    int o   = t / NTAP;
    unsigned bits = 0;
#pragma unroll
    for (int c = 0; c < 32; c++) {
        float v = M[((size_t)(o * CI + cw * 32 + c)) * NTAP + tap];
        bits |= (v >= 0.0f ? 1u : 0u) << c;
    }
    g_Wpk[idx] = bits;
}

// Per (o,tap) total weight popcount (for border correction)
__global__ void pw_kernel() {
    int idx = blockIdx.x * blockDim.x + threadIdx.x;
    if (idx >= CO * NTAP) return;
    int s = 0;
#pragma unroll
    for (int cw = 0; cw < CW; cw++) s += __popc(g_Wpk[idx * CW + cw]);
    g_PW[idx] = s;
}

// ---------------------------------------------------------------------------
// Main conv.
//  grid = (HH/TH, NB, NZ). Block: 8-row tile of one image, 32 o-channels.
//  224 threads laid out (56, 4); each thread owns TWO pixels: rows ty and
//  ty+4 (same column) -> every broadcast W-load feeds two independent
//  XOR/POPC chains (ILP-2), halving LDS per ALU op.
#define TH   8                 // rows per block
#define TSUB 4                 // thread-rows; each thread does rows ty, ty+TSUB
#define OG   8                 // o-channels per accumulator group
#define NZ   8                 // grid.z split of output channels
#define OPB  (CO / NZ)         // 32 o-channels per block
#define NTHREADS (WW * TSUB)   // 224

__global__ __launch_bounds__(NTHREADS, 4)
void bconv_kernel(const float* __restrict__ alpha, float* __restrict__ out) {
    __shared__ __align__(16) unsigned Asm[TH + 2][WW + 2][CW];   // 10*58*8*4 = 18,560 B
    __shared__ __align__(16) unsigned Wsm[OPB][NTAP][CW];        //  9,216 B
    __shared__ int   PWsm[OPB][NTAP];                            //  1,152 B
    __shared__ float Alp[OPB];                                   //    128 B

    const int tid    = threadIdx.x;
    const int h0     = blockIdx.x * TH;
    const int n      = blockIdx.y;
    const int obase0 = blockIdx.z * OPB;

    // --- stage activation tile (zero-padded) ---
    const int SITES = (TH + 2) * (WW + 2);          // 580
    for (int i = tid; i < CW * SITES; i += NTHREADS) {
        int cw  = i / SITES;
        int s   = i % SITES;
        int row = s / (WW + 2);
        int col = s % (WW + 2);
        int gh  = h0 - 1 + row;
        int gw  = col - 1;
        unsigned v = 0;
        if (gh >= 0 && gh < HH && gw >= 0 && gw < WW)
            v = g_Apk[(n * CW + cw) * HWSZ + gh * WW + gw];
        Asm[row][col][cw] = v;
    }
    // --- stage weights for this block's 32 o-channels ---
    for (int i = tid; i < OPB * NTAP * CW; i += NTHREADS)
        ((unsigned*)Wsm)[i] = g_Wpk[obase0 * NTAP * CW + i];
    for (int i = tid; i < OPB * NTAP; i += NTHREADS)
        ((int*)PWsm)[i] = g_PW[obase0 * NTAP + i];
    for (int i = tid; i < OPB; i += NTHREADS)
        Alp[i] = alpha[obase0 + i];

    __syncthreads();   // the ONLY barrier in this kernel

    const int tx = tid % WW;        // w
    const int ty = tid / WW;        // 0..3
    const int hA = h0 + ty;         // pixel 0 row
    const int hB = hA + TSUB;       // pixel 1 row
    const int w  = tx;

    const int ncols = 1 + (w > 0) + (w < WW - 1);
    const int nvA   = (1 + (hA > 0) + (hA < HH - 1)) * ncols;
    const int nvB   = (1 + (hB > 0) + (hB < HH - 1)) * ncols;
    const int hwA   = hA * WW + w;
    const int hwB   = hB * WW + w;
    const bool borderA = (nvA != 9);
    const bool borderB = (nvB != 9);

#pragma unroll 1
    for (int og = 0; og < OPB / OG; og++) {
        const int olocal = og * OG;

        int accA[OG], accB[OG];
#pragma unroll
        for (int o = 0; o < OG; o++) { accA[o] = 0; accB[o] = 0; }

#pragma unroll 1
        for (int tap = 0; tap < NTAP; tap++) {
            const int dy = tap / 3;
            const int dx = tap - dy * 3;
            const uint4* apA = (const uint4*)&Asm[ty + dy][tx + dx][0];
            const uint4 a0 = apA[0];
            const uint4 a1 = apA[1];
            const uint4* apB = (const uint4*)&Asm[ty + TSUB + dy][tx + dx][0];
            const uint4 b0 = apB[0];
            const uint4 b1 = apB[1];
#pragma unroll
            for (int o = 0; o < OG; o++) {
                const uint4* wp = (const uint4*)&Wsm[olocal + o][tap][0];
                const uint4 w0 = wp[0];
                const uint4 w1 = wp[1];
                int sa = (__popc(a0.x ^ w0.x) + __popc(a0.y ^ w0.y))
                       + (__popc(a0.z ^ w0.z) + __popc(a0.w ^ w0.w))
                       + (__popc(a1.x ^ w1.x) + __popc(a1.y ^ w1.y))
                       + (__popc(a1.z ^ w1.z) + __popc(a1.w ^ w1.w));
                int sb = (__popc(b0.x ^ w0.x) + __popc(b0.y ^ w0.y))
                       + (__popc(b0.z ^ w0.z) + __popc(b0.w ^ w0.w))
                       + (__popc(b1.x ^ w1.x) + __popc(b1.y ^ w1.y))
                       + (__popc(b1.z ^ w1.z) + __popc(b1.w ^ w1.w));
                accA[o] += sa;
                accB[o] += sb;
            }
        }

        // write outputs (border correction only when needed)
#pragma unroll
        for (int o = 0; o < OG; o++) {
            int corrA = 0, corrB = 0;
            if (borderA) {
#pragma unroll
                for (int tap = 0; tap < NTAP; tap++) {
                    int dy = tap / 3 - 1, dx = tap % 3 - 1;
                    int gh = hA + dy, gw = w + dx;
                    if (!(gh >= 0 && gh < HH && gw >= 0 && gw < WW))
                        corrA += PWsm[olocal + o][tap];
                }
            }
            if (borderB) {
#pragma unroll
                for (int tap = 0; tap < NTAP; tap++) {
                    int dy = tap / 3 - 1, dx = tap % 3 - 1;
                    int gh = hB + dy, gw = w + dx;
                    if (!(gh >= 0 && gh < HH && gw >= 0 && gw < WW))
                        corrB += PWsm[olocal + o][tap];
                }
            }
            const float al = Alp[olocal + o];
            const size_t base = ((size_t)(n * CO + obase0 + olocal + o)) * HWSZ;
            out[base + hwA] = al * (float)(nvA * 256 - 2 * accA[o] + 2 * corrA);
            out[base + hwB] = al * (float)(nvB * 256 - 2 * accB[o] + 2 * corrB);
        }
    }
}

// ---------------------------------------------------------------------------
extern "C" void kernel_launch(void* const* d_in, const int* in_sizes, int n_in,
                              void* d_out, int out_size) {
    const float* x     = (const float*)d_in[0];   // (32,256,56,56)
    const float* M     = (const float*)d_in[1];   // (256,256,3,3)
    const float* alpha = (const float*)d_in[2];   // (256,1,1)
    float* out         = (float*)d_out;           // (32,256,56,56)

    {
        int total = NB * CW * HWSZ;               // 802816
        pack_x_kernel<<<(total + 255) / 256, 256>>>(x);
    }
    {
        int total = CO * NTAP * CW;               // 18432
        pack_w_kernel<<<(total + 127) / 128, 128>>>(M);
    }
    {
        int total = CO * NTAP;                    // 2304
        pw_kernel<<<(total + 127) / 128, 128>>>();
    }
    {
        dim3 grid(HH / TH, NB, NZ);               // (7, 32, 8) = 1792 blocks
        bconv_kernel<<<grid, NTHREADS>>>(alpha, out);
    }
}